// round 14
// baseline (speedup 1.0000x reference)
#include <cuda_runtime.h>
#include <cuda_fp16.h>
#include <cstdint>
#include <math.h>

// Problem constants
#define L_SEQ 2000
#define D_FEAT 54
#define W_WIN 7
#define H_HEADS 3
#define HD_DIM 18
#define CH_CONV 32
#define CAT_DIM 108        // 2*D
#define K1_DIM 972         // per-ch feature dim (exact, no pad)
#define KFLAT (CH_CONV * K1_DIM)   // 31104 = 486 * 64
#define SPLITK 18
#define KT_CHUNK 27        // 486 / 18
#define N_DIM 256

// Scratch (device globals; no allocations allowed). uint4 for 16B alignment.
__device__ float g_f[L_SEQ * D_FEAT];
__device__ uint4 g_featsq[(size_t)L_SEQ * KFLAT / 8];          // half[2000][31104] ~124MB
__device__ uint4 g_w1hq[(size_t)1024 * N_DIM / 8];             // half[1024][256]
__device__ uint4 g_w2hq[(size_t)CH_CONV * N_DIM * N_DIM / 8];  // half[8192][256]
__device__ uint4 g_wchq[(size_t)KFLAT * N_DIM / 8];            // half[31104][256] flat Wcat
__device__ float g_bcp[CH_CONV * N_DIM];

// ---------------------------------------------------------------------------
// Prep: round W1 (972 real rows) and W2 to fp16, one kernel.
// ---------------------------------------------------------------------------
__global__ void prep_weights(const float* __restrict__ W1, __half* __restrict__ W1h,
                             const float* __restrict__ W2, __half* __restrict__ W2h) {
    int idx = blockIdx.x * 256 + threadIdx.x;
    if (idx < 1024 * N_DIM) {
        int k = idx >> 8;
        W1h[idx] = (k < K1_DIM) ? __float2half(W1[idx]) : __half(0.f);
    }
    int idx2 = idx - 1024 * N_DIM;
    if (idx2 >= 0 && idx2 < CH_CONV * N_DIM * N_DIM) W2h[idx2] = __float2half(W2[idx2]);
}

// bcp[ch][n] = sum_m b1[m] * W2[ch*256+m, n]
__global__ void bc_partial(const float* __restrict__ b1, const float* __restrict__ W2,
                           float* __restrict__ bcp) {
    int ch = blockIdx.x, n = threadIdx.x;
    float s = 0.f;
    for (int m = 0; m < 256; m++) s += b1[m] * W2[((size_t)ch * 256 + m) * 256 + n];
    bcp[ch * 256 + n] = s;
}

// out[i,n] = b2[n] + sum_ch bcp[ch,n]
__global__ void init_out(const float* __restrict__ bcp, const float* __restrict__ b2,
                         float* __restrict__ out) {
    int idx = blockIdx.x * 256 + threadIdx.x;
    if (idx < L_SEQ * N_DIM) {
        int n = idx & 255;
        float s = b2[n];
        #pragma unroll
        for (int ch = 0; ch < 32; ch++) s += bcp[ch * 256 + n];
        out[idx] = s;
    }
}

// ---------------------------------------------------------------------------
// Kernel A: f = beft @ W_bert + b_bert
// ---------------------------------------------------------------------------
__global__ void __launch_bounds__(256) bert_kernel(
        const float* __restrict__ beft, const float* __restrict__ Wb,
        const float* __restrict__ bb, float* __restrict__ f) {
    __shared__ float sh[4][1024];
    __shared__ float red[4][4][64];
    int r0 = blockIdx.x * 4;
    int tid = threadIdx.x;
    for (int idx = tid; idx < 4 * 1024; idx += 256)
        sh[idx >> 10][idx & 1023] = beft[(r0 + (idx >> 10)) * 1024 + (idx & 1023)];
    __syncthreads();
    int col = tid & 63;
    int ks = tid >> 6;
    float acc[4] = {0.f, 0.f, 0.f, 0.f};
    if (col < D_FEAT) {
        int kend = ks * 256 + 256;
        for (int k = ks * 256; k < kend; k++) {
            float w = Wb[k * D_FEAT + col];
            #pragma unroll
            for (int r = 0; r < 4; r++) acc[r] += sh[r][k] * w;
        }
    }
    #pragma unroll
    for (int r = 0; r < 4; r++) red[ks][r][col] = acc[r];
    __syncthreads();
    if (ks == 0 && col < D_FEAT) {
        float bias = bb[col];
        #pragma unroll
        for (int r = 0; r < 4; r++)
            f[(r0 + r) * D_FEAT + col] =
                red[0][r][col] + red[1][r][col] + red[2][r][col] + red[3][r][col] + bias;
    }
}

// ---------------------------------------------------------------------------
// FUSED Kernel B+C: attention (warp-per-residue, 2 passes) + conv branches
// + maxpool, writing feats directly.  conv input [nf|x] stays in smem.
// 8 residues per 256-thread block.
// ---------------------------------------------------------------------------
__global__ void __launch_bounds__(256) attn_conv_kernel(
        const float* __restrict__ f,
        const float* __restrict__ g1, const float* __restrict__ be1,
        const float* __restrict__ g2, const float* __restrict__ be2,
        const float* __restrict__ cw1, const float* __restrict__ cb1,
        const float* __restrict__ pa,
        const float* __restrict__ cw2, const float* __restrict__ cb2,
        const float* __restrict__ cw3, const float* __restrict__ cb3,
        __half* __restrict__ feats) {
    __shared__ float X[8][W_WIN][D_FEAT];
    __shared__ float NF[8][W_WIN][D_FEAT];
    __shared__ float P[8][H_HEADS][49];
    __shared__ float O[8][W_WIN][D_FEAT];
    __shared__ float w1s[96], w2s[160], w3s[224];
    __shared__ float b1s[32], b2s[32], b3s[32];
    __shared__ float pa_s;

    int t = threadIdx.x;
    int w = t >> 5, lane = t & 31;
    int i = blockIdx.x * 8 + w;
    float (*x)[D_FEAT] = X[w];
    float (*nf)[D_FEAT] = NF[w];
    float (*p)[49] = P[w];
    float (*o)[D_FEAT] = O[w];

    // conv weights (loaded in parallel with attn start; consumed after barrier)
    if (t < 96)  w1s[t] = cw1[t];
    if (t < 160) w2s[t] = cw2[t];
    if (t < 224) w3s[t] = cw3[t];
    if (t < 32) { b1s[t] = cb1[t]; b2s[t] = cb2[t]; b3s[t] = cb3[t]; }
    if (t == 0) pa_s = *pa;

    // ---- attention phase (warp-local) ----
    bool boundary = (i <= W_WIN) || (i + W_WIN >= L_SEQ);
    for (int e = lane; e < W_WIN * D_FEAT; e += 32) {
        int q = e / D_FEAT, c = e % D_FEAT;
        float v;
        if (boundary) v = (q == 0) ? f[i * D_FEAT + c] : 0.f;
        else          v = f[(i - 4 + q) * D_FEAT + c];
        x[q][c] = v; nf[q][c] = v;
    }
    __syncwarp();

    #pragma unroll
    for (int pass = 0; pass < 2; pass++) {
        const float* g  = pass ? g2 : g1;
        const float* bb = pass ? be2 : be1;
        for (int e = lane; e < H_HEADS * 49; e += 32) {
            int h = e / 49, r = e % 49, q = r / 7, k = r % 7;
            float s = 0.f;
            #pragma unroll
            for (int d = 0; d < HD_DIM; d++)
                s += x[q][h * HD_DIM + d] * x[k][h * HD_DIM + d];
            p[h][r] = s;
        }
        __syncwarp();
        if (lane < H_HEADS * W_WIN) {
            int h = lane / 7, q = lane % 7;
            float* pr = &p[h][q * 7];
            float mx = -1e30f;
            #pragma unroll
            for (int k = 0; k < 7; k++) mx = fmaxf(mx, pr[k]);
            float e[7], sum = 0.f;
            #pragma unroll
            for (int k = 0; k < 7; k++) { e[k] = expf(pr[k] - mx); sum += e[k]; }
            float inv = 1.f / sum;
            #pragma unroll
            for (int k = 0; k < 7; k++) pr[k] = e[k] * inv;
        }
        __syncwarp();
        for (int e = lane; e < W_WIN * D_FEAT; e += 32) {
            int q = e / D_FEAT, c = e % D_FEAT, h = c / HD_DIM;
            const float* pr = &p[h][q * 7];
            float s = 0.f;
            #pragma unroll
            for (int k = 0; k < 7; k++) s += pr[k] * x[k][c];
            o[q][c] = s;
        }
        __syncwarp();
        if (lane < W_WIN) {
            int q = lane;
            float m = 0.f;
            #pragma unroll
            for (int c = 0; c < D_FEAT; c++) m += o[q][c];
            m *= (1.f / D_FEAT);
            float v = 0.f;
            #pragma unroll
            for (int c = 0; c < D_FEAT; c++) { float d = o[q][c] - m; v += d * d; }
            v *= (1.f / D_FEAT);
            float r = rsqrtf(v + 1e-5f);
            #pragma unroll
            for (int c = 0; c < D_FEAT; c++)
                x[q][c] = (o[q][c] - m) * r * g[c] + bb[c];
        }
        __syncwarp();
    }
    __syncthreads();   // attn done for all 8 residues; conv phase follows

    // ---- conv phase: 8 residues x 32 ch x 27 col-pairs = 6912 items ----
    float a = pa_s;
    int i0 = blockIdx.x * 8;
    for (int item = t; item < 8 * CH_CONV * (CAT_DIM / 2); item += 256) {
        int r = item / (CH_CONV * (CAT_DIM / 2));
        int rem = item % (CH_CONV * (CAT_DIM / 2));
        int ch = rem / (CAT_DIM / 2);
        int wcol = (rem % (CAT_DIM / 2)) * 2;      // pair base; never straddles 53/54
        // column values for window rows -3..9 (13 rows, zero-padded)
        float c0[13], c1[13];
        #pragma unroll
        for (int h = 0; h < 13; h++) {
            float v0 = 0.f, v1 = 0.f;
            if (h >= 3 && h < 10) {
                int q = h - 3;
                if (wcol < D_FEAT) { v0 = NF[r][q][wcol]; v1 = NF[r][q][wcol + 1]; }
                else               { v0 = X[r][q][wcol - D_FEAT]; v1 = X[r][q][wcol - D_FEAT + 1]; }
            }
            c0[h] = v0; c1[h] = v1;
        }
        __half* fr = feats + (size_t)(i0 + r) * KFLAT + ch * K1_DIM;
        float o0[7], o1[7];

        // branch1: k=3, prelu, maxpool3 -> rows 0..4
        {
            const float* wp = &w1s[ch * 3];
            float bb = b1s[ch];
            #pragma unroll
            for (int h = 0; h < 7; h++) {
                float v0 = bb + wp[0]*c0[h+2] + wp[1]*c0[h+3] + wp[2]*c0[h+4];
                float v1 = bb + wp[0]*c1[h+2] + wp[1]*c1[h+3] + wp[2]*c1[h+4];
                o0[h] = (v0 >= 0.f) ? v0 : a * v0;
                o1[h] = (v1 >= 0.f) ? v1 : a * v1;
            }
            #pragma unroll
            for (int hp = 0; hp < 5; hp++)
                *(__half2*)&fr[hp * CAT_DIM + wcol] = __floats2half2_rn(
                    fmaxf(fmaxf(o0[hp], o0[hp+1]), o0[hp+2]),
                    fmaxf(fmaxf(o1[hp], o1[hp+1]), o1[hp+2]));
        }
        // branch2: k=5, relu, maxpool5 -> rows 0..2 (offset 540)
        {
            const float* wp = &w2s[ch * 5];
            float bb = b2s[ch];
            #pragma unroll
            for (int h = 0; h < 7; h++) {
                float v0 = bb, v1 = bb;
                #pragma unroll
                for (int tt = 0; tt < 5; tt++) {
                    v0 += wp[tt] * c0[h + 1 + tt];
                    v1 += wp[tt] * c1[h + 1 + tt];
                }
                o0[h] = fmaxf(v0, 0.f); o1[h] = fmaxf(v1, 0.f);
            }
            #pragma unroll
            for (int hp = 0; hp < 3; hp++) {
                float m0 = o0[hp], m1 = o1[hp];
                #pragma unroll
                for (int q = 1; q < 5; q++) { m0 = fmaxf(m0, o0[hp+q]); m1 = fmaxf(m1, o1[hp+q]); }
                *(__half2*)&fr[540 + hp * CAT_DIM + wcol] = __floats2half2_rn(m0, m1);
            }
        }
        // branch3: k=7, relu, maxpool7 -> 1 row (offset 864)
        {
            const float* wp = &w3s[ch * 7];
            float bb = b3s[ch];
            float m0 = -1e30f, m1 = -1e30f;
            #pragma unroll
            for (int h = 0; h < 7; h++) {
                float v0 = bb, v1 = bb;
                #pragma unroll
                for (int tt = 0; tt < 7; tt++) {
                    v0 += wp[tt] * c0[h + tt];
                    v1 += wp[tt] * c1[h + tt];
                }
                m0 = fmaxf(m0, fmaxf(v0, 0.f));
                m1 = fmaxf(m1, fmaxf(v1, 0.f));
            }
            *(__half2*)&fr[864 + wcol] = __floats2half2_rn(m0, m1);
        }
    }
}

// ---------------------------------------------------------------------------
// Wc-prep GEMM: Wcat[ch*972+j][n], j<972. 256 thr, 128x128, BK=64, 3-stage.
// ---------------------------------------------------------------------------
#define STAGE_BYTES 16384
#define HG_SMEM (6 * STAGE_BYTES)

__global__ void __launch_bounds__(256, 2) hgemm_wc(
        const __half* __restrict__ A,
        const __half* __restrict__ B, int KT,
        __half* __restrict__ Wcat) {
    extern __shared__ __align__(16) __half smem[];
    const int tid = threadIdx.x, lane = tid & 31, warp = tid >> 5;
    const int bn = blockIdx.x * 128, bm = blockIdx.y * 128;
    const int z = blockIdx.z;
    B += (size_t)z * N_DIM * N_DIM;
    const int wm = (warp >> 2) * 64, wn = (warp & 3) * 32;
    uint32_t sAu = (uint32_t)__cvta_generic_to_shared(&smem[0]);
    uint32_t sBu = sAu + 3 * STAGE_BYTES;

    float acc[4][4][4] = {};

    auto loadTile = [&](int kt, int st) {
        #pragma unroll
        for (int l = 0; l < 4; l++) {
            int j = tid + l * 256;
            int r = j >> 3, c = j & 7;
            int gr = min(bm + r, K1_DIM - 1);
            const __half* src = A + (size_t)gr * N_DIM + kt * 64 + c * 8;
            int cs = c ^ (r & 7);
            uint32_t dst = sAu + st * STAGE_BYTES + (uint32_t)(r * 64 + cs * 8) * 2;
            asm volatile("cp.async.cg.shared.global [%0], [%1], 16;" :: "r"(dst), "l"(src));
        }
        #pragma unroll
        for (int l = 0; l < 4; l++) {
            int j = tid + l * 256;
            int r = j >> 4, c = j & 15;
            const __half* src = B + (size_t)(kt * 64 + r) * N_DIM + bn + c * 8;
            int cs = c ^ (r & 7);
            uint32_t dst = sBu + st * STAGE_BYTES + (uint32_t)(r * 128 + cs * 8) * 2;
            asm volatile("cp.async.cg.shared.global [%0], [%1], 16;" :: "r"(dst), "l"(src));
        }
    };

    loadTile(0, 0);
    asm volatile("cp.async.commit_group;");
    if (KT > 1) { loadTile(1, 1); }
    asm volatile("cp.async.commit_group;");

    for (int kt = 0; kt < KT; kt++) {
        if (kt + 2 < KT) {
            loadTile(kt + 2, (kt + 2) % 3);
            asm volatile("cp.async.commit_group;");
            asm volatile("cp.async.wait_group 2;");
        } else if (kt + 2 == KT) {
            asm volatile("cp.async.wait_group 1;");
        } else {
            asm volatile("cp.async.wait_group 0;");
        }
        __syncthreads();
        const int st = kt % 3;
        #pragma unroll
        for (int ks = 0; ks < 4; ks++) {
            uint32_t a[4][4], b[4][2];
            #pragma unroll
            for (int mi = 0; mi < 4; mi++) {
                int r = wm + mi * 16 + (lane & 15);
                int cc = ks * 2 + (lane >> 4);
                int cs = cc ^ (r & 7);
                uint32_t addr = sAu + st * STAGE_BYTES + (uint32_t)(r * 64 + cs * 8) * 2;
                asm volatile("ldmatrix.sync.aligned.m8n8.x4.shared.b16 {%0,%1,%2,%3}, [%4];"
                    : "=r"(a[mi][0]), "=r"(a[mi][1]), "=r"(a[mi][2]), "=r"(a[mi][3])
                    : "r"(addr));
            }
            #pragma unroll
            for (int tp = 0; tp < 2; tp++) {
                int kr = ks * 16 + (lane & 15);
                int n0 = wn + (tp * 2 + (lane >> 4)) * 8;
                int cs = (n0 >> 3) ^ (kr & 7);
                uint32_t addr = sBu + st * STAGE_BYTES + (uint32_t)(kr * 128 + cs * 8) * 2;
                asm volatile("ldmatrix.sync.aligned.m8n8.x4.trans.shared.b16 {%0,%1,%2,%3}, [%4];"
                    : "=r"(b[tp*2][0]), "=r"(b[tp*2][1]), "=r"(b[tp*2+1][0]), "=r"(b[tp*2+1][1])
                    : "r"(addr));
            }
            #pragma unroll
            for (int mi = 0; mi < 4; mi++)
                #pragma unroll
                for (int ni = 0; ni < 4; ni++)
                    asm volatile(
                        "mma.sync.aligned.m16n8k16.row.col.f32.f16.f16.f32 "
                        "{%0,%1,%2,%3}, {%4,%5,%6,%7}, {%8,%9}, {%0,%1,%2,%3};"
                        : "+f"(acc[mi][ni][0]), "+f"(acc[mi][ni][1]),
                          "+f"(acc[mi][ni][2]), "+f"(acc[mi][ni][3])
                        : "r"(a[mi][0]), "r"(a[mi][1]), "r"(a[mi][2]), "r"(a[mi][3]),
                          "r"(b[ni][0]), "r"(b[ni][1]));
        }
        __syncthreads();
    }

    __half* base = Wcat + (size_t)z * K1_DIM * N_DIM;
    #pragma unroll
    for (int mi = 0; mi < 4; mi++) {
        int r0 = bm + wm + mi * 16 + (lane >> 2);
        #pragma unroll
        for (int ni = 0; ni < 4; ni++) {
            int col = bn + wn + ni * 8 + (lane & 3) * 2;
            if (r0 < K1_DIM)
                *(__half2*)(base + (size_t)r0 * N_DIM + col) =
                    __floats2half2_rn(acc[mi][ni][0], acc[mi][ni][1]);
            if (r0 + 8 < K1_DIM)
                *(__half2*)(base + (size_t)(r0 + 8) * N_DIM + col) =
                    __floats2half2_rn(acc[mi][ni][2], acc[mi][ni][3]);
        }
    }
}

// ---------------------------------------------------------------------------
// Main GEMM (flat): out(2000,256) += F(2000,31104) @ Wcat(31104,256)
// Split-K 18 x 27 tiles of BK=64 (exact). 128 thr, warp 64x64, 3-stage.
// ---------------------------------------------------------------------------
#define MGS 16384
#define MG_SMEM (6 * MGS)

__global__ void __launch_bounds__(128, 2) hgemm_main(
        const __half* __restrict__ F, const __half* __restrict__ Wcat,
        float* __restrict__ out) {
    extern __shared__ __align__(16) __half smem[];
    const int tid = threadIdx.x, lane = tid & 31, warp = tid >> 5;
    const int bn = blockIdx.x * 128;
    const int bm = blockIdx.y * 128;
    const int t0 = blockIdx.z * KT_CHUNK;
    const int wm = (warp >> 1) * 64;
    const int wn = (warp & 1) * 64;
    uint32_t sAu = (uint32_t)__cvta_generic_to_shared(&smem[0]);
    uint32_t sBu = sAu + 3 * MGS;

    float acc[4][8][4] = {};

    auto loadTile = [&](int kt, int st) {
        int kg = (t0 + kt) * 64;
        #pragma unroll
        for (int l = 0; l < 8; l++) {
            int j = tid + l * 128;
            int r = j >> 3, c = j & 7;
            int gr = min(bm + r, L_SEQ - 1);
            const __half* src = F + (size_t)gr * KFLAT + kg + c * 8;
            int cs = c ^ (r & 7);
            uint32_t dst = sAu + st * MGS + (uint32_t)(r * 64 + cs * 8) * 2;
            asm volatile("cp.async.cg.shared.global [%0], [%1], 16;" :: "r"(dst), "l"(src));
        }
        #pragma unroll
        for (int l = 0; l < 8; l++) {
            int j = tid + l * 128;
            int r = j >> 4, c = j & 15;
            const __half* src = Wcat + (size_t)(kg + r) * N_DIM + bn + c * 8;
            int cs = c ^ (r & 7);
            uint32_t dst = sBu + st * MGS + (uint32_t)(r * 128 + cs * 8) * 2;
            asm volatile("cp.async.cg.shared.global [%0], [%1], 16;" :: "r"(dst), "l"(src));
        }
    };

    loadTile(0, 0);
    asm volatile("cp.async.commit_group;");
    loadTile(1, 1);
    asm volatile("cp.async.commit_group;");

    for (int kt = 0; kt < KT_CHUNK; kt++) {
        if (kt + 2 < KT_CHUNK) {
            loadTile(kt + 2, (kt + 2) % 3);
            asm volatile("cp.async.commit_group;");
            asm volatile("cp.async.wait_group 2;");
        } else if (kt + 2 == KT_CHUNK) {
            asm volatile("cp.async.wait_group 1;");
        } else {
            asm volatile("cp.async.wait_group 0;");
        }
        __syncthreads();
        const int st = kt % 3;
        #pragma unroll
        for (int ks = 0; ks < 4; ks++) {
            uint32_t a[4][4], b[8][2];
            #pragma unroll
            for (int mi = 0; mi < 4; mi++) {
                int r = wm + mi * 16 + (lane & 15);
                int cc = ks * 2 + (lane >> 4);
                int cs = cc ^ (r & 7);
                uint32_t addr = sAu + st * MGS + (uint32_t)(r * 64 + cs * 8) * 2;
                asm volatile("ldmatrix.sync.aligned.m8n8.x4.shared.b16 {%0,%1,%2,%3}, [%4];"
                    : "=r"(a[mi][0]), "=r"(a[mi][1]), "=r"(a[mi][2]), "=r"(a[mi][3])
                    : "r"(addr));
            }
            #pragma unroll
            for (int tp = 0; tp < 4; tp++) {
                int kr = ks * 16 + (lane & 15);
                int n0 = wn + (tp * 2 + (lane >> 4)) * 8;
                int cs = (n0 >> 3) ^ (kr & 7);
                uint32_t addr = sBu + st * MGS + (uint32_t)(kr * 128 + cs * 8) * 2;
                asm volatile("ldmatrix.sync.aligned.m8n8.x4.trans.shared.b16 {%0,%1,%2,%3}, [%4];"
                    : "=r"(b[tp*2][0]), "=r"(b[tp*2][1]), "=r"(b[tp*2+1][0]), "=r"(b[tp*2+1][1])
                    : "r"(addr));
            }
            #pragma unroll
            for (int mi = 0; mi < 4; mi++)
                #pragma unroll
                for (int ni = 0; ni < 8; ni++)
                    asm volatile(
                        "mma.sync.aligned.m16n8k16.row.col.f32.f16.f16.f32 "
                        "{%0,%1,%2,%3}, {%4,%5,%6,%7}, {%8,%9}, {%0,%1,%2,%3};"
                        : "+f"(acc[mi][ni][0]), "+f"(acc[mi][ni][1]),
                          "+f"(acc[mi][ni][2]), "+f"(acc[mi][ni][3])
                        : "r"(a[mi][0]), "r"(a[mi][1]), "r"(a[mi][2]), "r"(a[mi][3]),
                          "r"(b[ni][0]), "r"(b[ni][1]));
        }
        __syncthreads();
    }

    #pragma unroll
    for (int mi = 0; mi < 4; mi++) {
        int r0 = bm + wm + mi * 16 + (lane >> 2);
        #pragma unroll
        for (int ni = 0; ni < 8; ni++) {
            int col = bn + wn + ni * 8 + (lane & 3) * 2;
            if (r0 < L_SEQ) {
                atomicAdd(&out[(size_t)r0 * N_DIM + col],     acc[mi][ni][0]);
                atomicAdd(&out[(size_t)r0 * N_DIM + col + 1], acc[mi][ni][1]);
            }
            if (r0 + 8 < L_SEQ) {
                atomicAdd(&out[(size_t)(r0 + 8) * N_DIM + col],     acc[mi][ni][2]);
                atomicAdd(&out[(size_t)(r0 + 8) * N_DIM + col + 1], acc[mi][ni][3]);
            }
        }
    }
}

// ---------------------------------------------------------------------------
// Final: in-place leaky relu on out
// ---------------------------------------------------------------------------
__global__ void leaky_inplace(float* __restrict__ out) {
    int idx = blockIdx.x * 256 + threadIdx.x;
    if (idx < L_SEQ * N_DIM) {
        float s = out[idx];
        out[idx] = (s >= 0.f) ? s : 0.01f * s;
    }
}

// ---------------------------------------------------------------------------
extern "C" void kernel_launch(void* const* d_in, const int* in_sizes, int n_in,
                              void* d_out, int out_size) {
    const float* beft   = (const float*)d_in[0];
    const float* Wb     = (const float*)d_in[4];
    const float* bb     = (const float*)d_in[5];
    const float* ln_g1  = (const float*)d_in[6];
    const float* ln_b1  = (const float*)d_in[7];
    const float* ln_g2  = (const float*)d_in[8];
    const float* ln_b2  = (const float*)d_in[9];
    const float* cw1    = (const float*)d_in[10];
    const float* cb1    = (const float*)d_in[11];
    const float* pa     = (const float*)d_in[12];
    const float* cw2    = (const float*)d_in[13];
    const float* cb2    = (const float*)d_in[14];
    const float* cw3    = (const float*)d_in[15];
    const float* cb3    = (const float*)d_in[16];
    const float* W1     = (const float*)d_in[17];
    const float* b1     = (const float*)d_in[18];
    const float* W2     = (const float*)d_in[19];
    const float* b2     = (const float*)d_in[20];
    float* out = (float*)d_out;

    float* f   = nullptr; cudaGetSymbolAddress((void**)&f, g_f);
    __half* feats = nullptr; cudaGetSymbolAddress((void**)&feats, g_featsq);
    __half* w1h   = nullptr; cudaGetSymbolAddress((void**)&w1h, g_w1hq);
    __half* w2h   = nullptr; cudaGetSymbolAddress((void**)&w2h, g_w2hq);
    __half* wcat  = nullptr; cudaGetSymbolAddress((void**)&wcat, g_wchq);
    float* bcp    = nullptr; cudaGetSymbolAddress((void**)&bcp, g_bcp);

    cudaFuncSetAttribute(hgemm_wc, cudaFuncAttributeMaxDynamicSharedMemorySize, HG_SMEM);
    cudaFuncSetAttribute(hgemm_main, cudaFuncAttributeMaxDynamicSharedMemorySize, MG_SMEM);

    // Side stream + events, created once outside capture.
    static cudaStream_t s2 = nullptr;
    static cudaEvent_t eFork = nullptr, eJoin = nullptr;
    if (!s2) {
        cudaStreamCreateWithFlags(&s2, cudaStreamNonBlocking);
        cudaEventCreateWithFlags(&eFork, cudaEventDisableTiming);
        cudaEventCreateWithFlags(&eJoin, cudaEventDisableTiming);
    }

    // Fork: weight-prep chain on s2, activation chain on the default stream.
    cudaEventRecord(eFork, 0);
    cudaStreamWaitEvent(s2, eFork, 0);

    // --- s2: weight prep + bias folding + out init + Wcat GEMM ---
    {
        int total = 1024 * N_DIM + CH_CONV * N_DIM * N_DIM;
        prep_weights<<<(total + 255) / 256, 256, 0, s2>>>(W1, w1h, W2, w2h);
    }
    bc_partial<<<CH_CONV, 256, 0, s2>>>(b1, W2, bcp);
    init_out<<<(L_SEQ * N_DIM + 255) / 256, 256, 0, s2>>>(bcp, b2, out);
    {
        dim3 grid(2, 8, CH_CONV);
        hgemm_wc<<<grid, 256, HG_SMEM, s2>>>(w1h, w2h, N_DIM / 64, wcat);
    }
    cudaEventRecord(eJoin, s2);

    // --- default stream: activations (bert -> fused attn+conv) ---
    bert_kernel<<<L_SEQ / 4, 256>>>(beft, Wb, bb, f);
    attn_conv_kernel<<<L_SEQ / 8, 256>>>(f, ln_g1, ln_b1, ln_g2, ln_b2,
                                         cw1, cb1, pa, cw2, cb2, cw3, cb3, feats);

    // Join, then flat split-K GEMM
    cudaStreamWaitEvent(0, eJoin, 0);
    {
        dim3 grid(2, 16, SPLITK);   // (n-tiles, m-tiles, k-chunks) = 576 CTAs
        hgemm_main<<<grid, 128, MG_SMEM>>>(feats, wcat, out);
    }

    // out = leaky(out)
    leaky_inplace<<<(L_SEQ * N_DIM + 255) / 256, 256>>>(out);
}

// round 15
// speedup vs baseline: 1.0487x; 1.0487x over previous
#include <cuda_runtime.h>
#include <cuda_fp16.h>
#include <cstdint>
#include <math.h>

// Problem constants
#define L_SEQ 2000
#define D_FEAT 54
#define W_WIN 7
#define H_HEADS 3
#define HD_DIM 18
#define CH_CONV 32
#define CAT_DIM 108        // 2*D
#define K1_DIM 972         // per-ch feature dim (exact, no pad)
#define KFLAT (CH_CONV * K1_DIM)   // 31104 = 486 * 64
#define SPLITK 9
#define KT_CHUNK 54        // 486 / 9
#define N_DIM 256

// Scratch (device globals; no allocations allowed). uint4 for 16B alignment.
__device__ float g_f[L_SEQ * D_FEAT];
__device__ float g_cat[L_SEQ * W_WIN * CAT_DIM];
__device__ uint4 g_featsq[(size_t)L_SEQ * KFLAT / 8];          // half[2000][31104] ~124MB
__device__ uint4 g_w1hq[(size_t)1024 * N_DIM / 8];             // half[1024][256]
__device__ uint4 g_w2hq[(size_t)CH_CONV * N_DIM * N_DIM / 8];  // half[8192][256]
__device__ uint4 g_wchq[(size_t)KFLAT * N_DIM / 8];            // half[31104][256] flat Wcat
__device__ float g_bcp[CH_CONV * N_DIM];

// ---------------------------------------------------------------------------
// Prep: round W1 (972 real rows) and W2 to fp16, one kernel.
// ---------------------------------------------------------------------------
__global__ void prep_weights(const float* __restrict__ W1, __half* __restrict__ W1h,
                             const float* __restrict__ W2, __half* __restrict__ W2h) {
    int idx = blockIdx.x * 256 + threadIdx.x;
    if (idx < 1024 * N_DIM) {
        int k = idx >> 8;
        W1h[idx] = (k < K1_DIM) ? __float2half(W1[idx]) : __half(0.f);
    }
    int idx2 = idx - 1024 * N_DIM;
    if (idx2 >= 0 && idx2 < CH_CONV * N_DIM * N_DIM) W2h[idx2] = __float2half(W2[idx2]);
}

// bcp[ch][n] = sum_m b1[m] * W2[ch*256+m, n]
__global__ void bc_partial(const float* __restrict__ b1, const float* __restrict__ W2,
                           float* __restrict__ bcp) {
    int ch = blockIdx.x, n = threadIdx.x;
    float s = 0.f;
    for (int m = 0; m < 256; m++) s += b1[m] * W2[((size_t)ch * 256 + m) * 256 + n];
    bcp[ch * 256 + n] = s;
}

// out[i,n] = b2[n] + sum_ch bcp[ch,n]
__global__ void init_out(const float* __restrict__ bcp, const float* __restrict__ b2,
                         float* __restrict__ out) {
    int idx = blockIdx.x * 256 + threadIdx.x;
    if (idx < L_SEQ * N_DIM) {
        int n = idx & 255;
        float s = b2[n];
        #pragma unroll
        for (int ch = 0; ch < 32; ch++) s += bcp[ch * 256 + n];
        out[idx] = s;
    }
}

// ---------------------------------------------------------------------------
// Kernel A: f = beft @ W_bert + b_bert
// ---------------------------------------------------------------------------
__global__ void __launch_bounds__(256) bert_kernel(
        const float* __restrict__ beft, const float* __restrict__ Wb,
        const float* __restrict__ bb, float* __restrict__ f) {
    __shared__ float sh[4][1024];
    __shared__ float red[4][4][64];
    int r0 = blockIdx.x * 4;
    int tid = threadIdx.x;
    for (int idx = tid; idx < 4 * 1024; idx += 256)
        sh[idx >> 10][idx & 1023] = beft[(r0 + (idx >> 10)) * 1024 + (idx & 1023)];
    __syncthreads();
    int col = tid & 63;
    int ks = tid >> 6;
    float acc[4] = {0.f, 0.f, 0.f, 0.f};
    if (col < D_FEAT) {
        int kend = ks * 256 + 256;
        for (int k = ks * 256; k < kend; k++) {
            float w = Wb[k * D_FEAT + col];
            #pragma unroll
            for (int r = 0; r < 4; r++) acc[r] += sh[r][k] * w;
        }
    }
    #pragma unroll
    for (int r = 0; r < 4; r++) red[ks][r][col] = acc[r];
    __syncthreads();
    if (ks == 0 && col < D_FEAT) {
        float bias = bb[col];
        #pragma unroll
        for (int r = 0; r < 4; r++)
            f[(r0 + r) * D_FEAT + col] =
                red[0][r][col] + red[1][r][col] + red[2][r][col] + red[3][r][col] + bias;
    }
}

// ---------------------------------------------------------------------------
// Kernel B: warp-per-residue attention (2 passes) -> cat
// ---------------------------------------------------------------------------
__global__ void __launch_bounds__(256) attn_kernel(
        const float* __restrict__ f,
        const float* __restrict__ g1, const float* __restrict__ be1,
        const float* __restrict__ g2, const float* __restrict__ be2,
        float* __restrict__ cat) {
    __shared__ float X[8][W_WIN][D_FEAT];
    __shared__ float NF[8][W_WIN][D_FEAT];
    __shared__ float P[8][H_HEADS][49];
    __shared__ float O[8][W_WIN][D_FEAT];

    int w = threadIdx.x >> 5, lane = threadIdx.x & 31;
    int i = blockIdx.x * 8 + w;
    float (*x)[D_FEAT] = X[w];
    float (*nf)[D_FEAT] = NF[w];
    float (*p)[49] = P[w];
    float (*o)[D_FEAT] = O[w];

    bool boundary = (i <= W_WIN) || (i + W_WIN >= L_SEQ);
    for (int e = lane; e < W_WIN * D_FEAT; e += 32) {
        int q = e / D_FEAT, c = e % D_FEAT;
        float v;
        if (boundary) v = (q == 0) ? f[i * D_FEAT + c] : 0.f;
        else          v = f[(i - 4 + q) * D_FEAT + c];
        x[q][c] = v; nf[q][c] = v;
    }
    __syncwarp();

    #pragma unroll
    for (int pass = 0; pass < 2; pass++) {
        const float* g  = pass ? g2 : g1;
        const float* bb = pass ? be2 : be1;
        for (int e = lane; e < H_HEADS * 49; e += 32) {
            int h = e / 49, r = e % 49, q = r / 7, k = r % 7;
            float s = 0.f;
            #pragma unroll
            for (int d = 0; d < HD_DIM; d++)
                s += x[q][h * HD_DIM + d] * x[k][h * HD_DIM + d];
            p[h][r] = s;
        }
        __syncwarp();
        if (lane < H_HEADS * W_WIN) {
            int h = lane / 7, q = lane % 7;
            float* pr = &p[h][q * 7];
            float mx = -1e30f;
            #pragma unroll
            for (int k = 0; k < 7; k++) mx = fmaxf(mx, pr[k]);
            float e[7], sum = 0.f;
            #pragma unroll
            for (int k = 0; k < 7; k++) { e[k] = expf(pr[k] - mx); sum += e[k]; }
            float inv = 1.f / sum;
            #pragma unroll
            for (int k = 0; k < 7; k++) pr[k] = e[k] * inv;
        }
        __syncwarp();
        for (int e = lane; e < W_WIN * D_FEAT; e += 32) {
            int q = e / D_FEAT, c = e % D_FEAT, h = c / HD_DIM;
            const float* pr = &p[h][q * 7];
            float s = 0.f;
            #pragma unroll
            for (int k = 0; k < 7; k++) s += pr[k] * x[k][c];
            o[q][c] = s;
        }
        __syncwarp();
        if (lane < W_WIN) {
            int q = lane;
            float m = 0.f;
            #pragma unroll
            for (int c = 0; c < D_FEAT; c++) m += o[q][c];
            m *= (1.f / D_FEAT);
            float v = 0.f;
            #pragma unroll
            for (int c = 0; c < D_FEAT; c++) { float d = o[q][c] - m; v += d * d; }
            v *= (1.f / D_FEAT);
            float r = rsqrtf(v + 1e-5f);
            #pragma unroll
            for (int c = 0; c < D_FEAT; c++)
                x[q][c] = (o[q][c] - m) * r * g[c] + bb[c];
        }
        __syncwarp();
    }

    for (int e = lane; e < W_WIN * CAT_DIM; e += 32) {
        int q = e / CAT_DIM, c = e % CAT_DIM;
        cat[i * (W_WIN * CAT_DIM) + e] = (c < D_FEAT) ? nf[q][c] : x[q][c - D_FEAT];
    }
}

// ---------------------------------------------------------------------------
// Kernel C: conv branches + act + maxpool -> feats fp16, FLAT layout
// feats[i][ch*972 + j], j in 0..971 (no padding).
// ---------------------------------------------------------------------------
__global__ void __launch_bounds__(256) conv_kernel(
        const float* __restrict__ cat,
        const float* __restrict__ cw1, const float* __restrict__ cb1,
        const float* __restrict__ pa,
        const float* __restrict__ cw2, const float* __restrict__ cb2,
        const float* __restrict__ cw3, const float* __restrict__ cb3,
        __half* __restrict__ feats) {
    int i = blockIdx.x;
    int t = threadIdx.x;
    __shared__ float xp[13][CAT_DIM];
    __shared__ float w1s[96], w2s[160], w3s[224];
    __shared__ float b1s[32], b2s[32], b3s[32];

    for (int idx = t; idx < 13 * CAT_DIM; idx += 256) {
        int h = idx / CAT_DIM, w = idx % CAT_DIM;
        xp[h][w] = (h >= 3 && h < 10) ? cat[i * (W_WIN * CAT_DIM) + (h - 3) * CAT_DIM + w] : 0.f;
    }
    if (t < 96)  w1s[t] = cw1[t];
    if (t < 160) w2s[t] = cw2[t];
    if (t < 224) w3s[t] = cw3[t];
    if (t < 32) { b1s[t] = cb1[t]; b2s[t] = cb2[t]; b3s[t] = cb3[t]; }
    float a = *pa;
    __syncthreads();

    __half* base = feats + (size_t)i * KFLAT;

    for (int pp = t; pp < CH_CONV * (CAT_DIM / 2); pp += 256) {
        int ch = pp / (CAT_DIM / 2), w = (pp % (CAT_DIM / 2)) * 2;
        float c0[13], c1[13];
        #pragma unroll
        for (int h = 0; h < 13; h++) { c0[h] = xp[h][w]; c1[h] = xp[h][w + 1]; }
        __half* fr = base + ch * K1_DIM;
        float o0[7], o1[7];

        {
            const float* wp = &w1s[ch * 3];
            float bb = b1s[ch];
            #pragma unroll
            for (int h = 0; h < 7; h++) {
                float v0 = bb + wp[0]*c0[h+2] + wp[1]*c0[h+3] + wp[2]*c0[h+4];
                float v1 = bb + wp[0]*c1[h+2] + wp[1]*c1[h+3] + wp[2]*c1[h+4];
                o0[h] = (v0 >= 0.f) ? v0 : a * v0;
                o1[h] = (v1 >= 0.f) ? v1 : a * v1;
            }
            #pragma unroll
            for (int hp = 0; hp < 5; hp++)
                *(__half2*)&fr[hp * CAT_DIM + w] = __floats2half2_rn(
                    fmaxf(fmaxf(o0[hp], o0[hp+1]), o0[hp+2]),
                    fmaxf(fmaxf(o1[hp], o1[hp+1]), o1[hp+2]));
        }
        {
            const float* wp = &w2s[ch * 5];
            float bb = b2s[ch];
            #pragma unroll
            for (int h = 0; h < 7; h++) {
                float v0 = bb, v1 = bb;
                #pragma unroll
                for (int tt = 0; tt < 5; tt++) {
                    v0 += wp[tt] * c0[h + 1 + tt];
                    v1 += wp[tt] * c1[h + 1 + tt];
                }
                o0[h] = fmaxf(v0, 0.f); o1[h] = fmaxf(v1, 0.f);
            }
            #pragma unroll
            for (int hp = 0; hp < 3; hp++) {
                float m0 = o0[hp], m1 = o1[hp];
                #pragma unroll
                for (int q = 1; q < 5; q++) { m0 = fmaxf(m0, o0[hp+q]); m1 = fmaxf(m1, o1[hp+q]); }
                *(__half2*)&fr[540 + hp * CAT_DIM + w] = __floats2half2_rn(m0, m1);
            }
        }
        {
            const float* wp = &w3s[ch * 7];
            float bb = b3s[ch];
            float m0 = -1e30f, m1 = -1e30f;
            #pragma unroll
            for (int h = 0; h < 7; h++) {
                float v0 = bb, v1 = bb;
                #pragma unroll
                for (int tt = 0; tt < 7; tt++) {
                    v0 += wp[tt] * c0[h + tt];
                    v1 += wp[tt] * c1[h + tt];
                }
                m0 = fmaxf(m0, fmaxf(v0, 0.f));
                m1 = fmaxf(m1, fmaxf(v1, 0.f));
            }
            *(__half2*)&fr[864 + w] = __floats2half2_rn(m0, m1);
        }
    }
}

// ---------------------------------------------------------------------------
// Wc-prep GEMM: Wcat[ch*972+j][n], j<972. 256 thr, 128x128, BK=64, 3-stage.
// ---------------------------------------------------------------------------
#define STAGE_BYTES 16384
#define HG_SMEM (6 * STAGE_BYTES)

__global__ void __launch_bounds__(256, 2) hgemm_wc(
        const __half* __restrict__ A,
        const __half* __restrict__ B, int KT,
        __half* __restrict__ Wcat) {
    extern __shared__ __align__(16) __half smem[];
    const int tid = threadIdx.x, lane = tid & 31, warp = tid >> 5;
    const int bn = blockIdx.x * 128, bm = blockIdx.y * 128;
    const int z = blockIdx.z;
    B += (size_t)z * N_DIM * N_DIM;
    const int wm = (warp >> 2) * 64, wn = (warp & 3) * 32;
    uint32_t sAu = (uint32_t)__cvta_generic_to_shared(&smem[0]);
    uint32_t sBu = sAu + 3 * STAGE_BYTES;

    float acc[4][4][4] = {};

    auto loadTile = [&](int kt, int st) {
        #pragma unroll
        for (int l = 0; l < 4; l++) {
            int j = tid + l * 256;
            int r = j >> 3, c = j & 7;
            int gr = min(bm + r, K1_DIM - 1);
            const __half* src = A + (size_t)gr * N_DIM + kt * 64 + c * 8;
            int cs = c ^ (r & 7);
            uint32_t dst = sAu + st * STAGE_BYTES + (uint32_t)(r * 64 + cs * 8) * 2;
            asm volatile("cp.async.cg.shared.global [%0], [%1], 16;" :: "r"(dst), "l"(src));
        }
        #pragma unroll
        for (int l = 0; l < 4; l++) {
            int j = tid + l * 256;
            int r = j >> 4, c = j & 15;
            const __half* src = B + (size_t)(kt * 64 + r) * N_DIM + bn + c * 8;
            int cs = c ^ (r & 7);
            uint32_t dst = sBu + st * STAGE_BYTES + (uint32_t)(r * 128 + cs * 8) * 2;
            asm volatile("cp.async.cg.shared.global [%0], [%1], 16;" :: "r"(dst), "l"(src));
        }
    };

    loadTile(0, 0);
    asm volatile("cp.async.commit_group;");
    if (KT > 1) { loadTile(1, 1); }
    asm volatile("cp.async.commit_group;");

    for (int kt = 0; kt < KT; kt++) {
        if (kt + 2 < KT) {
            loadTile(kt + 2, (kt + 2) % 3);
            asm volatile("cp.async.commit_group;");
            asm volatile("cp.async.wait_group 2;");
        } else if (kt + 2 == KT) {
            asm volatile("cp.async.wait_group 1;");
        } else {
            asm volatile("cp.async.wait_group 0;");
        }
        __syncthreads();
        const int st = kt % 3;
        #pragma unroll
        for (int ks = 0; ks < 4; ks++) {
            uint32_t a[4][4], b[4][2];
            #pragma unroll
            for (int mi = 0; mi < 4; mi++) {
                int r = wm + mi * 16 + (lane & 15);
                int cc = ks * 2 + (lane >> 4);
                int cs = cc ^ (r & 7);
                uint32_t addr = sAu + st * STAGE_BYTES + (uint32_t)(r * 64 + cs * 8) * 2;
                asm volatile("ldmatrix.sync.aligned.m8n8.x4.shared.b16 {%0,%1,%2,%3}, [%4];"
                    : "=r"(a[mi][0]), "=r"(a[mi][1]), "=r"(a[mi][2]), "=r"(a[mi][3])
                    : "r"(addr));
            }
            #pragma unroll
            for (int tp = 0; tp < 2; tp++) {
                int kr = ks * 16 + (lane & 15);
                int n0 = wn + (tp * 2 + (lane >> 4)) * 8;
                int cs = (n0 >> 3) ^ (kr & 7);
                uint32_t addr = sBu + st * STAGE_BYTES + (uint32_t)(kr * 128 + cs * 8) * 2;
                asm volatile("ldmatrix.sync.aligned.m8n8.x4.trans.shared.b16 {%0,%1,%2,%3}, [%4];"
                    : "=r"(b[tp*2][0]), "=r"(b[tp*2][1]), "=r"(b[tp*2+1][0]), "=r"(b[tp*2+1][1])
                    : "r"(addr));
            }
            #pragma unroll
            for (int mi = 0; mi < 4; mi++)
                #pragma unroll
                for (int ni = 0; ni < 4; ni++)
                    asm volatile(
                        "mma.sync.aligned.m16n8k16.row.col.f32.f16.f16.f32 "
                        "{%0,%1,%2,%3}, {%4,%5,%6,%7}, {%8,%9}, {%0,%1,%2,%3};"
                        : "+f"(acc[mi][ni][0]), "+f"(acc[mi][ni][1]),
                          "+f"(acc[mi][ni][2]), "+f"(acc[mi][ni][3])
                        : "r"(a[mi][0]), "r"(a[mi][1]), "r"(a[mi][2]), "r"(a[mi][3]),
                          "r"(b[ni][0]), "r"(b[ni][1]));
        }
        __syncthreads();
    }

    __half* base = Wcat + (size_t)z * K1_DIM * N_DIM;
    #pragma unroll
    for (int mi = 0; mi < 4; mi++) {
        int r0 = bm + wm + mi * 16 + (lane >> 2);
        #pragma unroll
        for (int ni = 0; ni < 4; ni++) {
            int col = bn + wn + ni * 8 + (lane & 3) * 2;
            if (r0 < K1_DIM)
                *(__half2*)(base + (size_t)r0 * N_DIM + col) =
                    __floats2half2_rn(acc[mi][ni][0], acc[mi][ni][1]);
            if (r0 + 8 < K1_DIM)
                *(__half2*)(base + (size_t)(r0 + 8) * N_DIM + col) =
                    __floats2half2_rn(acc[mi][ni][2], acc[mi][ni][3]);
        }
    }
}

// ---------------------------------------------------------------------------
// Main GEMM (flat): out(2000,256) += F(2000,31104) @ Wcat(31104,256)
// Split-K 9 x 54 tiles of BK=64 (exact) -> 288 CTAs = ONE wave at 2 CTA/SM.
// 128 thr, warp 64x64 (2x2), CTA 128x128, 3-stage.
// ---------------------------------------------------------------------------
#define MGS 16384
#define MG_SMEM (6 * MGS)

__global__ void __launch_bounds__(128, 2) hgemm_main(
        const __half* __restrict__ F, const __half* __restrict__ Wcat,
        float* __restrict__ out) {
    extern __shared__ __align__(16) __half smem[];
    const int tid = threadIdx.x, lane = tid & 31, warp = tid >> 5;
    const int bn = blockIdx.x * 128;
    const int bm = blockIdx.y * 128;
    const int t0 = blockIdx.z * KT_CHUNK;
    const int wm = (warp >> 1) * 64;
    const int wn = (warp & 1) * 64;
    uint32_t sAu = (uint32_t)__cvta_generic_to_shared(&smem[0]);
    uint32_t sBu = sAu + 3 * MGS;

    float acc[4][8][4] = {};

    auto loadTile = [&](int kt, int st) {
        int kg = (t0 + kt) * 64;
        #pragma unroll
        for (int l = 0; l < 8; l++) {
            int j = tid + l * 128;
            int r = j >> 3, c = j & 7;
            int gr = min(bm + r, L_SEQ - 1);
            const __half* src = F + (size_t)gr * KFLAT + kg + c * 8;
            int cs = c ^ (r & 7);
            uint32_t dst = sAu + st * MGS + (uint32_t)(r * 64 + cs * 8) * 2;
            asm volatile("cp.async.cg.shared.global [%0], [%1], 16;" :: "r"(dst), "l"(src));
        }
        #pragma unroll
        for (int l = 0; l < 8; l++) {
            int j = tid + l * 128;
            int r = j >> 4, c = j & 15;
            const __half* src = Wcat + (size_t)(kg + r) * N_DIM + bn + c * 8;
            int cs = c ^ (r & 7);
            uint32_t dst = sBu + st * MGS + (uint32_t)(r * 128 + cs * 8) * 2;
            asm volatile("cp.async.cg.shared.global [%0], [%1], 16;" :: "r"(dst), "l"(src));
        }
    };

    loadTile(0, 0);
    asm volatile("cp.async.commit_group;");
    loadTile(1, 1);
    asm volatile("cp.async.commit_group;");

    for (int kt = 0; kt < KT_CHUNK; kt++) {
        if (kt + 2 < KT_CHUNK) {
            loadTile(kt + 2, (kt + 2) % 3);
            asm volatile("cp.async.commit_group;");
            asm volatile("cp.async.wait_group 2;");
        } else if (kt + 2 == KT_CHUNK) {
            asm volatile("cp.async.wait_group 1;");
        } else {
            asm volatile("cp.async.wait_group 0;");
        }
        __syncthreads();
        const int st = kt % 3;
        #pragma unroll
        for (int ks = 0; ks < 4; ks++) {
            uint32_t a[4][4], b[8][2];
            #pragma unroll
            for (int mi = 0; mi < 4; mi++) {
                int r = wm + mi * 16 + (lane & 15);
                int cc = ks * 2 + (lane >> 4);
                int cs = cc ^ (r & 7);
                uint32_t addr = sAu + st * MGS + (uint32_t)(r * 64 + cs * 8) * 2;
                asm volatile("ldmatrix.sync.aligned.m8n8.x4.shared.b16 {%0,%1,%2,%3}, [%4];"
                    : "=r"(a[mi][0]), "=r"(a[mi][1]), "=r"(a[mi][2]), "=r"(a[mi][3])
                    : "r"(addr));
            }
            #pragma unroll
            for (int tp = 0; tp < 4; tp++) {
                int kr = ks * 16 + (lane & 15);
                int n0 = wn + (tp * 2 + (lane >> 4)) * 8;
                int cs = (n0 >> 3) ^ (kr & 7);
                uint32_t addr = sBu + st * MGS + (uint32_t)(kr * 128 + cs * 8) * 2;
                asm volatile("ldmatrix.sync.aligned.m8n8.x4.trans.shared.b16 {%0,%1,%2,%3}, [%4];"
                    : "=r"(b[tp*2][0]), "=r"(b[tp*2][1]), "=r"(b[tp*2+1][0]), "=r"(b[tp*2+1][1])
                    : "r"(addr));
            }
            #pragma unroll
            for (int mi = 0; mi < 4; mi++)
                #pragma unroll
                for (int ni = 0; ni < 8; ni++)
                    asm volatile(
                        "mma.sync.aligned.m16n8k16.row.col.f32.f16.f16.f32 "
                        "{%0,%1,%2,%3}, {%4,%5,%6,%7}, {%8,%9}, {%0,%1,%2,%3};"
                        : "+f"(acc[mi][ni][0]), "+f"(acc[mi][ni][1]),
                          "+f"(acc[mi][ni][2]), "+f"(acc[mi][ni][3])
                        : "r"(a[mi][0]), "r"(a[mi][1]), "r"(a[mi][2]), "r"(a[mi][3]),
                          "r"(b[ni][0]), "r"(b[ni][1]));
        }
        __syncthreads();
    }

    #pragma unroll
    for (int mi = 0; mi < 4; mi++) {
        int r0 = bm + wm + mi * 16 + (lane >> 2);
        #pragma unroll
        for (int ni = 0; ni < 8; ni++) {
            int col = bn + wn + ni * 8 + (lane & 3) * 2;
            if (r0 < L_SEQ) {
                atomicAdd(&out[(size_t)r0 * N_DIM + col],     acc[mi][ni][0]);
                atomicAdd(&out[(size_t)r0 * N_DIM + col + 1], acc[mi][ni][1]);
            }
            if (r0 + 8 < L_SEQ) {
                atomicAdd(&out[(size_t)(r0 + 8) * N_DIM + col],     acc[mi][ni][2]);
                atomicAdd(&out[(size_t)(r0 + 8) * N_DIM + col + 1], acc[mi][ni][3]);
            }
        }
    }
}

// ---------------------------------------------------------------------------
// Final: in-place leaky relu on out
// ---------------------------------------------------------------------------
__global__ void leaky_inplace(float* __restrict__ out) {
    int idx = blockIdx.x * 256 + threadIdx.x;
    if (idx < L_SEQ * N_DIM) {
        float s = out[idx];
        out[idx] = (s >= 0.f) ? s : 0.01f * s;
    }
}

// ---------------------------------------------------------------------------
extern "C" void kernel_launch(void* const* d_in, const int* in_sizes, int n_in,
                              void* d_out, int out_size) {
    const float* beft   = (const float*)d_in[0];
    const float* Wb     = (const float*)d_in[4];
    const float* bb     = (const float*)d_in[5];
    const float* ln_g1  = (const float*)d_in[6];
    const float* ln_b1  = (const float*)d_in[7];
    const float* ln_g2  = (const float*)d_in[8];
    const float* ln_b2  = (const float*)d_in[9];
    const float* cw1    = (const float*)d_in[10];
    const float* cb1    = (const float*)d_in[11];
    const float* pa     = (const float*)d_in[12];
    const float* cw2    = (const float*)d_in[13];
    const float* cb2    = (const float*)d_in[14];
    const float* cw3    = (const float*)d_in[15];
    const float* cb3    = (const float*)d_in[16];
    const float* W1     = (const float*)d_in[17];
    const float* b1     = (const float*)d_in[18];
    const float* W2     = (const float*)d_in[19];
    const float* b2     = (const float*)d_in[20];
    float* out = (float*)d_out;

    float* f   = nullptr; cudaGetSymbolAddress((void**)&f, g_f);
    float* cat = nullptr; cudaGetSymbolAddress((void**)&cat, g_cat);
    __half* feats = nullptr; cudaGetSymbolAddress((void**)&feats, g_featsq);
    __half* w1h   = nullptr; cudaGetSymbolAddress((void**)&w1h, g_w1hq);
    __half* w2h   = nullptr; cudaGetSymbolAddress((void**)&w2h, g_w2hq);
    __half* wcat  = nullptr; cudaGetSymbolAddress((void**)&wcat, g_wchq);
    float* bcp    = nullptr; cudaGetSymbolAddress((void**)&bcp, g_bcp);

    cudaFuncSetAttribute(hgemm_wc, cudaFuncAttributeMaxDynamicSharedMemorySize, HG_SMEM);
    cudaFuncSetAttribute(hgemm_main, cudaFuncAttributeMaxDynamicSharedMemorySize, MG_SMEM);

    // Side stream + events, created once outside capture.
    static cudaStream_t s2 = nullptr;
    static cudaEvent_t eFork = nullptr, eJoin = nullptr;
    if (!s2) {
        cudaStreamCreateWithFlags(&s2, cudaStreamNonBlocking);
        cudaEventCreateWithFlags(&eFork, cudaEventDisableTiming);
        cudaEventCreateWithFlags(&eJoin, cudaEventDisableTiming);
    }

    // Fork: weight-prep chain on s2, activation chain on the default stream.
    cudaEventRecord(eFork, 0);
    cudaStreamWaitEvent(s2, eFork, 0);

    // --- s2: weight prep + bias folding + out init + Wcat GEMM ---
    {
        int total = 1024 * N_DIM + CH_CONV * N_DIM * N_DIM;
        prep_weights<<<(total + 255) / 256, 256, 0, s2>>>(W1, w1h, W2, w2h);
    }
    bc_partial<<<CH_CONV, 256, 0, s2>>>(b1, W2, bcp);
    init_out<<<(L_SEQ * N_DIM + 255) / 256, 256, 0, s2>>>(bcp, b2, out);
    {
        dim3 grid(2, 8, CH_CONV);
        hgemm_wc<<<grid, 256, HG_SMEM, s2>>>(w1h, w2h, N_DIM / 64, wcat);
    }
    cudaEventRecord(eJoin, s2);

    // --- default stream: activations ---
    bert_kernel<<<L_SEQ / 4, 256>>>(beft, Wb, bb, f);
    attn_kernel<<<L_SEQ / 8, 256>>>(f, ln_g1, ln_b1, ln_g2, ln_b2, cat);
    conv_kernel<<<L_SEQ, 256>>>(cat, cw1, cb1, pa, cw2, cb2, cw3, cb3, feats);

    // Join, then flat split-K GEMM (single wave)
    cudaStreamWaitEvent(0, eJoin, 0);
    {
        dim3 grid(2, 16, SPLITK);   // (n-tiles, m-tiles, k-chunks) = 288 CTAs
        hgemm_main<<<grid, 128, MG_SMEM>>>(feats, wcat, out);
    }

    // out = leaky(out)
    leaky_inplace<<<(L_SEQ * N_DIM + 255) / 256, 256>>>(out);
}

// round 16
// speedup vs baseline: 1.0499x; 1.0012x over previous
#include <cuda_runtime.h>
#include <cuda_fp16.h>
#include <cstdint>
#include <math.h>

// Problem constants
#define L_SEQ 2000
#define D_FEAT 54
#define W_WIN 7
#define H_HEADS 3
#define HD_DIM 18
#define CH_CONV 32
#define CAT_DIM 108        // 2*D
#define K1_DIM 972         // per-ch feature dim (exact, no pad)
#define KFLAT (CH_CONV * K1_DIM)   // 31104 = 486 * 64
#define SPLITK 9
#define KT_CHUNK 54        // 486 / 9
#define N_DIM 256

// Scratch (device globals; no allocations allowed). uint4 for 16B alignment.
__device__ float g_f[L_SEQ * D_FEAT];
__device__ float g_cat[L_SEQ * W_WIN * CAT_DIM];
__device__ uint4 g_featsq[(size_t)L_SEQ * KFLAT / 8];          // half[2000][31104] ~124MB
__device__ uint4 g_w1hq[(size_t)1024 * N_DIM / 8];             // half[1024][256]
__device__ uint4 g_w2hq[(size_t)CH_CONV * N_DIM * N_DIM / 8];  // half[8192][256]
__device__ uint4 g_wchq[(size_t)KFLAT * N_DIM / 8];            // half[31104][256] flat Wcat
__device__ float g_bcp[CH_CONV * N_DIM];

// ---------------------------------------------------------------------------
// Prep: round W1 (972 real rows) and W2 to fp16, one kernel.
// ---------------------------------------------------------------------------
__global__ void prep_weights(const float* __restrict__ W1, __half* __restrict__ W1h,
                             const float* __restrict__ W2, __half* __restrict__ W2h) {
    int idx = blockIdx.x * 256 + threadIdx.x;
    if (idx < 1024 * N_DIM) {
        int k = idx >> 8;
        W1h[idx] = (k < K1_DIM) ? __float2half(W1[idx]) : __half(0.f);
    }
    int idx2 = idx - 1024 * N_DIM;
    if (idx2 >= 0 && idx2 < CH_CONV * N_DIM * N_DIM) W2h[idx2] = __float2half(W2[idx2]);
}

// bcp[ch][n] = sum_m b1[m] * W2[ch*256+m, n]
__global__ void bc_partial(const float* __restrict__ b1, const float* __restrict__ W2,
                           float* __restrict__ bcp) {
    int ch = blockIdx.x, n = threadIdx.x;
    float s = 0.f;
    for (int m = 0; m < 256; m++) s += b1[m] * W2[((size_t)ch * 256 + m) * 256 + n];
    bcp[ch * 256 + n] = s;
}

// out[i,n] = b2[n] + sum_ch bcp[ch,n]
__global__ void init_out(const float* __restrict__ bcp, const float* __restrict__ b2,
                         float* __restrict__ out) {
    int idx = blockIdx.x * 256 + threadIdx.x;
    if (idx < L_SEQ * N_DIM) {
        int n = idx & 255;
        float s = b2[n];
        #pragma unroll
        for (int ch = 0; ch < 32; ch++) s += bcp[ch * 256 + n];
        out[idx] = s;
    }
}

// ---------------------------------------------------------------------------
// Kernel A: f = beft @ W_bert + b_bert   (8 rows/block, 512 thr, 8-way K-split)
// ---------------------------------------------------------------------------
__global__ void __launch_bounds__(512) bert_kernel(
        const float* __restrict__ beft, const float* __restrict__ Wb,
        const float* __restrict__ bb, float* __restrict__ f) {
    __shared__ float sh[8][1024];            // 32 KB
    __shared__ float red[8][8][64];          // 16 KB  [ks][r][col]
    int r0 = blockIdx.x * 8;
    int tid = threadIdx.x;
    // float4 fill: 8 rows x 1024 floats = 2048 float4
    const float4* src = (const float4*)(beft + (size_t)r0 * 1024);
    float4* dst = (float4*)&sh[0][0];
    #pragma unroll
    for (int l = 0; l < 4; l++) dst[tid + l * 512] = src[tid + l * 512];
    __syncthreads();

    int col = tid & 63;          // 0..63 (54 used)
    int ks  = tid >> 6;          // 0..7
    float acc[8] = {};
    if (col < D_FEAT) {
        int k0 = ks * 128, kend = k0 + 128;
        for (int k = k0; k < kend; k++) {
            float w = Wb[k * D_FEAT + col];
            #pragma unroll
            for (int r = 0; r < 8; r++) acc[r] += sh[r][k] * w;
        }
    }
    #pragma unroll
    for (int r = 0; r < 8; r++) red[ks][r][col] = acc[r];
    __syncthreads();
    // each ks-group writes row r = ks
    if (col < D_FEAT) {
        float s = bb[col];
        #pragma unroll
        for (int q = 0; q < 8; q++) s += red[q][ks][col];
        f[(r0 + ks) * D_FEAT + col] = s;
    }
}

// ---------------------------------------------------------------------------
// Kernel B: warp-per-residue attention (2 passes) -> cat
// ---------------------------------------------------------------------------
__global__ void __launch_bounds__(256) attn_kernel(
        const float* __restrict__ f,
        const float* __restrict__ g1, const float* __restrict__ be1,
        const float* __restrict__ g2, const float* __restrict__ be2,
        float* __restrict__ cat) {
    __shared__ float X[8][W_WIN][D_FEAT];
    __shared__ float NF[8][W_WIN][D_FEAT];
    __shared__ float P[8][H_HEADS][49];
    __shared__ float O[8][W_WIN][D_FEAT];

    int w = threadIdx.x >> 5, lane = threadIdx.x & 31;
    int i = blockIdx.x * 8 + w;
    float (*x)[D_FEAT] = X[w];
    float (*nf)[D_FEAT] = NF[w];
    float (*p)[49] = P[w];
    float (*o)[D_FEAT] = O[w];

    bool boundary = (i <= W_WIN) || (i + W_WIN >= L_SEQ);
    for (int e = lane; e < W_WIN * D_FEAT; e += 32) {
        int q = e / D_FEAT, c = e % D_FEAT;
        float v;
        if (boundary) v = (q == 0) ? f[i * D_FEAT + c] : 0.f;
        else          v = f[(i - 4 + q) * D_FEAT + c];
        x[q][c] = v; nf[q][c] = v;
    }
    __syncwarp();

    #pragma unroll
    for (int pass = 0; pass < 2; pass++) {
        const float* g  = pass ? g2 : g1;
        const float* bb = pass ? be2 : be1;
        for (int e = lane; e < H_HEADS * 49; e += 32) {
            int h = e / 49, r = e % 49, q = r / 7, k = r % 7;
            float s = 0.f;
            #pragma unroll
            for (int d = 0; d < HD_DIM; d++)
                s += x[q][h * HD_DIM + d] * x[k][h * HD_DIM + d];
            p[h][r] = s;
        }
        __syncwarp();
        if (lane < H_HEADS * W_WIN) {
            int h = lane / 7, q = lane % 7;
            float* pr = &p[h][q * 7];
            float mx = -1e30f;
            #pragma unroll
            for (int k = 0; k < 7; k++) mx = fmaxf(mx, pr[k]);
            float e[7], sum = 0.f;
            #pragma unroll
            for (int k = 0; k < 7; k++) { e[k] = expf(pr[k] - mx); sum += e[k]; }
            float inv = 1.f / sum;
            #pragma unroll
            for (int k = 0; k < 7; k++) pr[k] = e[k] * inv;
        }
        __syncwarp();
        for (int e = lane; e < W_WIN * D_FEAT; e += 32) {
            int q = e / D_FEAT, c = e % D_FEAT, h = c / HD_DIM;
            const float* pr = &p[h][q * 7];
            float s = 0.f;
            #pragma unroll
            for (int k = 0; k < 7; k++) s += pr[k] * x[k][c];
            o[q][c] = s;
        }
        __syncwarp();
        if (lane < W_WIN) {
            int q = lane;
            float m = 0.f;
            #pragma unroll
            for (int c = 0; c < D_FEAT; c++) m += o[q][c];
            m *= (1.f / D_FEAT);
            float v = 0.f;
            #pragma unroll
            for (int c = 0; c < D_FEAT; c++) { float d = o[q][c] - m; v += d * d; }
            v *= (1.f / D_FEAT);
            float r = rsqrtf(v + 1e-5f);
            #pragma unroll
            for (int c = 0; c < D_FEAT; c++)
                x[q][c] = (o[q][c] - m) * r * g[c] + bb[c];
        }
        __syncwarp();
    }

    for (int e = lane; e < W_WIN * CAT_DIM; e += 32) {
        int q = e / CAT_DIM, c = e % CAT_DIM;
        cat[i * (W_WIN * CAT_DIM) + e] = (c < D_FEAT) ? nf[q][c] : x[q][c - D_FEAT];
    }
}

// ---------------------------------------------------------------------------
// Kernel C: conv branches + act + maxpool -> feats fp16, FLAT layout
// ---------------------------------------------------------------------------
__global__ void __launch_bounds__(256) conv_kernel(
        const float* __restrict__ cat,
        const float* __restrict__ cw1, const float* __restrict__ cb1,
        const float* __restrict__ pa,
        const float* __restrict__ cw2, const float* __restrict__ cb2,
        const float* __restrict__ cw3, const float* __restrict__ cb3,
        __half* __restrict__ feats) {
    int i = blockIdx.x;
    int t = threadIdx.x;
    __shared__ float xp[13][CAT_DIM];
    __shared__ float w1s[96], w2s[160], w3s[224];
    __shared__ float b1s[32], b2s[32], b3s[32];

    for (int idx = t; idx < 13 * CAT_DIM; idx += 256) {
        int h = idx / CAT_DIM, w = idx % CAT_DIM;
        xp[h][w] = (h >= 3 && h < 10) ? cat[i * (W_WIN * CAT_DIM) + (h - 3) * CAT_DIM + w] : 0.f;
    }
    if (t < 96)  w1s[t] = cw1[t];
    if (t < 160) w2s[t] = cw2[t];
    if (t < 224) w3s[t] = cw3[t];
    if (t < 32) { b1s[t] = cb1[t]; b2s[t] = cb2[t]; b3s[t] = cb3[t]; }
    float a = *pa;
    __syncthreads();

    __half* base = feats + (size_t)i * KFLAT;

    for (int pp = t; pp < CH_CONV * (CAT_DIM / 2); pp += 256) {
        int ch = pp / (CAT_DIM / 2), w = (pp % (CAT_DIM / 2)) * 2;
        float c0[13], c1[13];
        #pragma unroll
        for (int h = 0; h < 13; h++) { c0[h] = xp[h][w]; c1[h] = xp[h][w + 1]; }
        __half* fr = base + ch * K1_DIM;
        float o0[7], o1[7];

        {
            const float* wp = &w1s[ch * 3];
            float bb = b1s[ch];
            #pragma unroll
            for (int h = 0; h < 7; h++) {
                float v0 = bb + wp[0]*c0[h+2] + wp[1]*c0[h+3] + wp[2]*c0[h+4];
                float v1 = bb + wp[0]*c1[h+2] + wp[1]*c1[h+3] + wp[2]*c1[h+4];
                o0[h] = (v0 >= 0.f) ? v0 : a * v0;
                o1[h] = (v1 >= 0.f) ? v1 : a * v1;
            }
            #pragma unroll
            for (int hp = 0; hp < 5; hp++)
                *(__half2*)&fr[hp * CAT_DIM + w] = __floats2half2_rn(
                    fmaxf(fmaxf(o0[hp], o0[hp+1]), o0[hp+2]),
                    fmaxf(fmaxf(o1[hp], o1[hp+1]), o1[hp+2]));
        }
        {
            const float* wp = &w2s[ch * 5];
            float bb = b2s[ch];
            #pragma unroll
            for (int h = 0; h < 7; h++) {
                float v0 = bb, v1 = bb;
                #pragma unroll
                for (int tt = 0; tt < 5; tt++) {
                    v0 += wp[tt] * c0[h + 1 + tt];
                    v1 += wp[tt] * c1[h + 1 + tt];
                }
                o0[h] = fmaxf(v0, 0.f); o1[h] = fmaxf(v1, 0.f);
            }
            #pragma unroll
            for (int hp = 0; hp < 3; hp++) {
                float m0 = o0[hp], m1 = o1[hp];
                #pragma unroll
                for (int q = 1; q < 5; q++) { m0 = fmaxf(m0, o0[hp+q]); m1 = fmaxf(m1, o1[hp+q]); }
                *(__half2*)&fr[540 + hp * CAT_DIM + w] = __floats2half2_rn(m0, m1);
            }
        }
        {
            const float* wp = &w3s[ch * 7];
            float bb = b3s[ch];
            float m0 = -1e30f, m1 = -1e30f;
            #pragma unroll
            for (int h = 0; h < 7; h++) {
                float v0 = bb, v1 = bb;
                #pragma unroll
                for (int tt = 0; tt < 7; tt++) {
                    v0 += wp[tt] * c0[h + tt];
                    v1 += wp[tt] * c1[h + tt];
                }
                m0 = fmaxf(m0, fmaxf(v0, 0.f));
                m1 = fmaxf(m1, fmaxf(v1, 0.f));
            }
            *(__half2*)&fr[864 + w] = __floats2half2_rn(m0, m1);
        }
    }
}

// ---------------------------------------------------------------------------
// Wc-prep GEMM: Wcat[ch*972+j][n], j<972. 256 thr, 128x128, BK=64, 3-stage.
// ---------------------------------------------------------------------------
#define STAGE_BYTES 16384
#define HG_SMEM (6 * STAGE_BYTES)

__global__ void __launch_bounds__(256, 2) hgemm_wc(
        const __half* __restrict__ A,
        const __half* __restrict__ B, int KT,
        __half* __restrict__ Wcat) {
    extern __shared__ __align__(16) __half smem[];
    const int tid = threadIdx.x, lane = tid & 31, warp = tid >> 5;
    const int bn = blockIdx.x * 128, bm = blockIdx.y * 128;
    const int z = blockIdx.z;
    B += (size_t)z * N_DIM * N_DIM;
    const int wm = (warp >> 2) * 64, wn = (warp & 3) * 32;
    uint32_t sAu = (uint32_t)__cvta_generic_to_shared(&smem[0]);
    uint32_t sBu = sAu + 3 * STAGE_BYTES;

    float acc[4][4][4] = {};

    auto loadTile = [&](int kt, int st) {
        #pragma unroll
        for (int l = 0; l < 4; l++) {
            int j = tid + l * 256;
            int r = j >> 3, c = j & 7;
            int gr = min(bm + r, K1_DIM - 1);
            const __half* src = A + (size_t)gr * N_DIM + kt * 64 + c * 8;
            int cs = c ^ (r & 7);
            uint32_t dst = sAu + st * STAGE_BYTES + (uint32_t)(r * 64 + cs * 8) * 2;
            asm volatile("cp.async.cg.shared.global [%0], [%1], 16;" :: "r"(dst), "l"(src));
        }
        #pragma unroll
        for (int l = 0; l < 4; l++) {
            int j = tid + l * 256;
            int r = j >> 4, c = j & 15;
            const __half* src = B + (size_t)(kt * 64 + r) * N_DIM + bn + c * 8;
            int cs = c ^ (r & 7);
            uint32_t dst = sBu + st * STAGE_BYTES + (uint32_t)(r * 128 + cs * 8) * 2;
            asm volatile("cp.async.cg.shared.global [%0], [%1], 16;" :: "r"(dst), "l"(src));
        }
    };

    loadTile(0, 0);
    asm volatile("cp.async.commit_group;");
    if (KT > 1) { loadTile(1, 1); }
    asm volatile("cp.async.commit_group;");

    for (int kt = 0; kt < KT; kt++) {
        if (kt + 2 < KT) {
            loadTile(kt + 2, (kt + 2) % 3);
            asm volatile("cp.async.commit_group;");
            asm volatile("cp.async.wait_group 2;");
        } else if (kt + 2 == KT) {
            asm volatile("cp.async.wait_group 1;");
        } else {
            asm volatile("cp.async.wait_group 0;");
        }
        __syncthreads();
        const int st = kt % 3;
        #pragma unroll
        for (int ks = 0; ks < 4; ks++) {
            uint32_t a[4][4], b[4][2];
            #pragma unroll
            for (int mi = 0; mi < 4; mi++) {
                int r = wm + mi * 16 + (lane & 15);
                int cc = ks * 2 + (lane >> 4);
                int cs = cc ^ (r & 7);
                uint32_t addr = sAu + st * STAGE_BYTES + (uint32_t)(r * 64 + cs * 8) * 2;
                asm volatile("ldmatrix.sync.aligned.m8n8.x4.shared.b16 {%0,%1,%2,%3}, [%4];"
                    : "=r"(a[mi][0]), "=r"(a[mi][1]), "=r"(a[mi][2]), "=r"(a[mi][3])
                    : "r"(addr));
            }
            #pragma unroll
            for (int tp = 0; tp < 2; tp++) {
                int kr = ks * 16 + (lane & 15);
                int n0 = wn + (tp * 2 + (lane >> 4)) * 8;
                int cs = (n0 >> 3) ^ (kr & 7);
                uint32_t addr = sBu + st * STAGE_BYTES + (uint32_t)(kr * 128 + cs * 8) * 2;
                asm volatile("ldmatrix.sync.aligned.m8n8.x4.trans.shared.b16 {%0,%1,%2,%3}, [%4];"
                    : "=r"(b[tp*2][0]), "=r"(b[tp*2][1]), "=r"(b[tp*2+1][0]), "=r"(b[tp*2+1][1])
                    : "r"(addr));
            }
            #pragma unroll
            for (int mi = 0; mi < 4; mi++)
                #pragma unroll
                for (int ni = 0; ni < 4; ni++)
                    asm volatile(
                        "mma.sync.aligned.m16n8k16.row.col.f32.f16.f16.f32 "
                        "{%0,%1,%2,%3}, {%4,%5,%6,%7}, {%8,%9}, {%0,%1,%2,%3};"
                        : "+f"(acc[mi][ni][0]), "+f"(acc[mi][ni][1]),
                          "+f"(acc[mi][ni][2]), "+f"(acc[mi][ni][3])
                        : "r"(a[mi][0]), "r"(a[mi][1]), "r"(a[mi][2]), "r"(a[mi][3]),
                          "r"(b[ni][0]), "r"(b[ni][1]));
        }
        __syncthreads();
    }

    __half* base = Wcat + (size_t)z * K1_DIM * N_DIM;
    #pragma unroll
    for (int mi = 0; mi < 4; mi++) {
        int r0 = bm + wm + mi * 16 + (lane >> 2);
        #pragma unroll
        for (int ni = 0; ni < 4; ni++) {
            int col = bn + wn + ni * 8 + (lane & 3) * 2;
            if (r0 < K1_DIM)
                *(__half2*)(base + (size_t)r0 * N_DIM + col) =
                    __floats2half2_rn(acc[mi][ni][0], acc[mi][ni][1]);
            if (r0 + 8 < K1_DIM)
                *(__half2*)(base + (size_t)(r0 + 8) * N_DIM + col) =
                    __floats2half2_rn(acc[mi][ni][2], acc[mi][ni][3]);
        }
    }
}

// ---------------------------------------------------------------------------
// Main GEMM (flat): out(2000,256) += F(2000,31104) @ Wcat(31104,256)
// Split-K 9 x 54 tiles of BK=64 (exact) -> 288 CTAs = ONE wave at 2 CTA/SM.
// ---------------------------------------------------------------------------
#define MGS 16384
#define MG_SMEM (6 * MGS)

__global__ void __launch_bounds__(128, 2) hgemm_main(
        const __half* __restrict__ F, const __half* __restrict__ Wcat,
        float* __restrict__ out) {
    extern __shared__ __align__(16) __half smem[];
    const int tid = threadIdx.x, lane = tid & 31, warp = tid >> 5;
    const int bn = blockIdx.x * 128;
    const int bm = blockIdx.y * 128;
    const int t0 = blockIdx.z * KT_CHUNK;
    const int wm = (warp >> 1) * 64;
    const int wn = (warp & 1) * 64;
    uint32_t sAu = (uint32_t)__cvta_generic_to_shared(&smem[0]);
    uint32_t sBu = sAu + 3 * MGS;

    float acc[4][8][4] = {};

    auto loadTile = [&](int kt, int st) {
        int kg = (t0 + kt) * 64;
        #pragma unroll
        for (int l = 0; l < 8; l++) {
            int j = tid + l * 128;
            int r = j >> 3, c = j & 7;
            int gr = min(bm + r, L_SEQ - 1);
            const __half* src = F + (size_t)gr * KFLAT + kg + c * 8;
            int cs = c ^ (r & 7);
            uint32_t dst = sAu + st * MGS + (uint32_t)(r * 64 + cs * 8) * 2;
            asm volatile("cp.async.cg.shared.global [%0], [%1], 16;" :: "r"(dst), "l"(src));
        }
        #pragma unroll
        for (int l = 0; l < 8; l++) {
            int j = tid + l * 128;
            int r = j >> 4, c = j & 15;
            const __half* src = Wcat + (size_t)(kg + r) * N_DIM + bn + c * 8;
            int cs = c ^ (r & 7);
            uint32_t dst = sBu + st * MGS + (uint32_t)(r * 128 + cs * 8) * 2;
            asm volatile("cp.async.cg.shared.global [%0], [%1], 16;" :: "r"(dst), "l"(src));
        }
    };

    loadTile(0, 0);
    asm volatile("cp.async.commit_group;");
    loadTile(1, 1);
    asm volatile("cp.async.commit_group;");

    for (int kt = 0; kt < KT_CHUNK; kt++) {
        if (kt + 2 < KT_CHUNK) {
            loadTile(kt + 2, (kt + 2) % 3);
            asm volatile("cp.async.commit_group;");
            asm volatile("cp.async.wait_group 2;");
        } else if (kt + 2 == KT_CHUNK) {
            asm volatile("cp.async.wait_group 1;");
        } else {
            asm volatile("cp.async.wait_group 0;");
        }
        __syncthreads();
        const int st = kt % 3;
        #pragma unroll
        for (int ks = 0; ks < 4; ks++) {
            uint32_t a[4][4], b[8][2];
            #pragma unroll
            for (int mi = 0; mi < 4; mi++) {
                int r = wm + mi * 16 + (lane & 15);
                int cc = ks * 2 + (lane >> 4);
                int cs = cc ^ (r & 7);
                uint32_t addr = sAu + st * MGS + (uint32_t)(r * 64 + cs * 8) * 2;
                asm volatile("ldmatrix.sync.aligned.m8n8.x4.shared.b16 {%0,%1,%2,%3}, [%4];"
                    : "=r"(a[mi][0]), "=r"(a[mi][1]), "=r"(a[mi][2]), "=r"(a[mi][3])
                    : "r"(addr));
            }
            #pragma unroll
            for (int tp = 0; tp < 4; tp++) {
                int kr = ks * 16 + (lane & 15);
                int n0 = wn + (tp * 2 + (lane >> 4)) * 8;
                int cs = (n0 >> 3) ^ (kr & 7);
                uint32_t addr = sBu + st * MGS + (uint32_t)(kr * 128 + cs * 8) * 2;
                asm volatile("ldmatrix.sync.aligned.m8n8.x4.trans.shared.b16 {%0,%1,%2,%3}, [%4];"
                    : "=r"(b[tp*2][0]), "=r"(b[tp*2][1]), "=r"(b[tp*2+1][0]), "=r"(b[tp*2+1][1])
                    : "r"(addr));
            }
            #pragma unroll
            for (int mi = 0; mi < 4; mi++)
                #pragma unroll
                for (int ni = 0; ni < 8; ni++)
                    asm volatile(
                        "mma.sync.aligned.m16n8k16.row.col.f32.f16.f16.f32 "
                        "{%0,%1,%2,%3}, {%4,%5,%6,%7}, {%8,%9}, {%0,%1,%2,%3};"
                        : "+f"(acc[mi][ni][0]), "+f"(acc[mi][ni][1]),
                          "+f"(acc[mi][ni][2]), "+f"(acc[mi][ni][3])
                        : "r"(a[mi][0]), "r"(a[mi][1]), "r"(a[mi][2]), "r"(a[mi][3]),
                          "r"(b[ni][0]), "r"(b[ni][1]));
        }
        __syncthreads();
    }

    #pragma unroll
    for (int mi = 0; mi < 4; mi++) {
        int r0 = bm + wm + mi * 16 + (lane >> 2);
        #pragma unroll
        for (int ni = 0; ni < 8; ni++) {
            int col = bn + wn + ni * 8 + (lane & 3) * 2;
            if (r0 < L_SEQ) {
                atomicAdd(&out[(size_t)r0 * N_DIM + col],     acc[mi][ni][0]);
                atomicAdd(&out[(size_t)r0 * N_DIM + col + 1], acc[mi][ni][1]);
            }
            if (r0 + 8 < L_SEQ) {
                atomicAdd(&out[(size_t)(r0 + 8) * N_DIM + col],     acc[mi][ni][2]);
                atomicAdd(&out[(size_t)(r0 + 8) * N_DIM + col + 1], acc[mi][ni][3]);
            }
        }
    }
}

// ---------------------------------------------------------------------------
// Final: in-place leaky relu on out
// ---------------------------------------------------------------------------
__global__ void leaky_inplace(float* __restrict__ out) {
    int idx = blockIdx.x * 256 + threadIdx.x;
    if (idx < L_SEQ * N_DIM) {
        float s = out[idx];
        out[idx] = (s >= 0.f) ? s : 0.01f * s;
    }
}

// ---------------------------------------------------------------------------
extern "C" void kernel_launch(void* const* d_in, const int* in_sizes, int n_in,
                              void* d_out, int out_size) {
    const float* beft   = (const float*)d_in[0];
    const float* Wb     = (const float*)d_in[4];
    const float* bb     = (const float*)d_in[5];
    const float* ln_g1  = (const float*)d_in[6];
    const float* ln_b1  = (const float*)d_in[7];
    const float* ln_g2  = (const float*)d_in[8];
    const float* ln_b2  = (const float*)d_in[9];
    const float* cw1    = (const float*)d_in[10];
    const float* cb1    = (const float*)d_in[11];
    const float* pa     = (const float*)d_in[12];
    const float* cw2    = (const float*)d_in[13];
    const float* cb2    = (const float*)d_in[14];
    const float* cw3    = (const float*)d_in[15];
    const float* cb3    = (const float*)d_in[16];
    const float* W1     = (const float*)d_in[17];
    const float* b1     = (const float*)d_in[18];
    const float* W2     = (const float*)d_in[19];
    const float* b2     = (const float*)d_in[20];
    float* out = (float*)d_out;

    float* f   = nullptr; cudaGetSymbolAddress((void**)&f, g_f);
    float* cat = nullptr; cudaGetSymbolAddress((void**)&cat, g_cat);
    __half* feats = nullptr; cudaGetSymbolAddress((void**)&feats, g_featsq);
    __half* w1h   = nullptr; cudaGetSymbolAddress((void**)&w1h, g_w1hq);
    __half* w2h   = nullptr; cudaGetSymbolAddress((void**)&w2h, g_w2hq);
    __half* wcat  = nullptr; cudaGetSymbolAddress((void**)&wcat, g_wchq);
    float* bcp    = nullptr; cudaGetSymbolAddress((void**)&bcp, g_bcp);

    cudaFuncSetAttribute(hgemm_wc, cudaFuncAttributeMaxDynamicSharedMemorySize, HG_SMEM);
    cudaFuncSetAttribute(hgemm_main, cudaFuncAttributeMaxDynamicSharedMemorySize, MG_SMEM);

    // Side stream + events, created once outside capture.
    static cudaStream_t s2 = nullptr;
    static cudaEvent_t eFork = nullptr, eJoin = nullptr;
    if (!s2) {
        cudaStreamCreateWithFlags(&s2, cudaStreamNonBlocking);
        cudaEventCreateWithFlags(&eFork, cudaEventDisableTiming);
        cudaEventCreateWithFlags(&eJoin, cudaEventDisableTiming);
    }

    // Fork: weight-prep chain on s2, activation chain on the default stream.
    cudaEventRecord(eFork, 0);
    cudaStreamWaitEvent(s2, eFork, 0);

    // --- s2: weight prep + bias folding + out init + Wcat GEMM ---
    {
        int total = 1024 * N_DIM + CH_CONV * N_DIM * N_DIM;
        prep_weights<<<(total + 255) / 256, 256, 0, s2>>>(W1, w1h, W2, w2h);
    }
    bc_partial<<<CH_CONV, 256, 0, s2>>>(b1, W2, bcp);
    init_out<<<(L_SEQ * N_DIM + 255) / 256, 256, 0, s2>>>(bcp, b2, out);
    {
        dim3 grid(2, 8, CH_CONV);
        hgemm_wc<<<grid, 256, HG_SMEM, s2>>>(w1h, w2h, N_DIM / 64, wcat);
    }
    cudaEventRecord(eJoin, s2);

    // --- default stream: activations ---
    bert_kernel<<<L_SEQ / 8, 512>>>(beft, Wb, bb, f);
    attn_kernel<<<L_SEQ / 8, 256>>>(f, ln_g1, ln_b1, ln_g2, ln_b2, cat);
    conv_kernel<<<L_SEQ, 256>>>(cat, cw1, cb1, pa, cw2, cb2, cw3, cb3, feats);

    // Join, then flat split-K GEMM (single wave)
    cudaStreamWaitEvent(0, eJoin, 0);
    {
        dim3 grid(2, 16, SPLITK);   // (n-tiles, m-tiles, k-chunks) = 288 CTAs
        hgemm_main<<<grid, 128, MG_SMEM>>>(feats, wcat, out);
    }

    // out = leaky(out)
    leaky_inplace<<<(L_SEQ * N_DIM + 255) / 256, 256>>>(out);
}